// round 8
// baseline (speedup 1.0000x reference)
#include <cuda_runtime.h>
#include <cstdint>

// Problem constants
#define B_   32
#define NQ_  16384
#define NK_  31
#define DM_  64
#define H_   4
#define DH_  16

#define NTHREADS 128

// log2(e) / sqrt(d_head)
#define LOG2E_OVER_SCALE 0.36067376022224085f

// Padded smem pitches (floats) chosen for conflict-free fragment LDS
#define KPAD  40     // Ksm[64 d][40]
#define VWPAD 72     // VWsm[128 k][72]
#define PPAD  40     // Psm per warp [16 rows][40]

// smem float offsets
#define OF_VW 0                         // 128*72   = 9216
#define OF_K  9216                      // 64*40    = 2560
#define OF_P  11776                     // 4*16*40  = 2560
#define OF_MO 14336                     // 32
#define OF_BI 14368                     // 64
#define SMEM_FLOATS 14432               // 57728 bytes

// Precomputed VW = per-head V_h @ W_h^T, concatenated along k: [b][128 k][72]
__device__ float g_vw[B_ * 128 * VWPAD];

// ---------------- helpers ----------------

__device__ __forceinline__ uint32_t hi_of(float v) {
    return __float_as_uint(v) & 0xFFFFE000u;            // tf32-exact high part
}
__device__ __forceinline__ uint32_t lo_of(float v, uint32_t h) {
    return __float_as_uint(v - __uint_as_float(h));     // exact residual
}
__device__ __forceinline__ float ex2f(float x) {
    float y;
    asm("ex2.approx.ftz.f32 %0, %1;" : "=f"(y) : "f"(x));
    return y;
}
__device__ __forceinline__ float rcpf(float x) {
    float y;
    asm("rcp.approx.ftz.f32 %0, %1;" : "=f"(y) : "f"(x));
    return y;
}

// D += A(tf32) * B(tf32), m16n8k8, A row-major, B col-major, fp32 accumulate
__device__ __forceinline__ void mma_tf32(float d[4],
                                         uint32_t a0, uint32_t a1,
                                         uint32_t a2, uint32_t a3,
                                         uint32_t b0, uint32_t b1) {
    asm volatile(
        "mma.sync.aligned.m16n8k8.row.col.f32.tf32.tf32.f32 "
        "{%0,%1,%2,%3}, {%4,%5,%6,%7}, {%8,%9}, {%0,%1,%2,%3};"
        : "+f"(d[0]), "+f"(d[1]), "+f"(d[2]), "+f"(d[3])
        : "r"(a0), "r"(a1), "r"(a2), "r"(a3), "r"(b0), "r"(b1));
}

// ===========================================================================
// Prep: VW[b][k = h*32+key][n] = sum_i V[b][key][h*16+i] * W[n][h*16+i]
// (key 31 is zero padding; masking handled in softmax)
// ===========================================================================

__global__ void __launch_bounds__(NTHREADS)
vw_prep(const float* __restrict__ V, const float* __restrict__ W)
{
    const int b = blockIdx.x;
    for (int idx = threadIdx.x; idx < 128 * 64; idx += NTHREADS) {
        int k = idx >> 6;          // 0..127
        int n = idx & 63;
        int h = k >> 5, key = k & 31;
        float acc = 0.f;
        if (key < NK_) {
            const float* vp = V + ((size_t)b * NK_ + key) * DM_ + h * DH_;
            const float* wp = W + n * DM_ + h * DH_;
#pragma unroll
            for (int i = 0; i < DH_; i++) acc += vp[i] * wp[i];
        }
        g_vw[(size_t)b * 128 * VWPAD + k * VWPAD + n] = acc;
    }
}

// ===========================================================================
// Main: QK (tensor, 3xTF32) -> softmax (C-frag regs) -> P@VW (tensor, 3xTF32)
// Block = 128 threads (4 warps); each warp does 2 m16 tiles -> 128 rows/block
// ===========================================================================

__global__ void __launch_bounds__(NTHREADS, 3)
mha_tc_kernel(const float* __restrict__ Q,
              const float* __restrict__ K,
              const int* __restrict__ mask,
              const float* __restrict__ bias,
              float* __restrict__ out)
{
    extern __shared__ float sm[];
    const int tid  = threadIdx.x;
    const int wid  = tid >> 5;
    const int lane = tid & 31;
    const int g    = lane >> 2;      // groupID (row within half-tile)
    const int tg   = lane & 3;       // threadID in group
    const int b    = blockIdx.y;

    // ---------------- stage VW, K^T, mask offsets, bias ----------------
    {
        const float4* src = (const float4*)(g_vw + (size_t)b * 128 * VWPAD);
        float4* dst = (float4*)(sm + OF_VW);
        for (int i = tid; i < 128 * VWPAD / 4; i += NTHREADS) dst[i] = src[i];

        const float* Kb = K + (size_t)b * NK_ * DM_;
        for (int i = tid; i < DM_ * 32; i += NTHREADS) {
            int d = i >> 5, key = i & 31;
            sm[OF_K + d * KPAD + key] = (key < NK_) ? Kb[key * DM_ + d] : 0.f;
        }
        if (tid < 32)
            sm[OF_MO + tid] = (tid < NK_ && mask[b * NK_ + tid] != 0) ? 0.f : -1e30f;
        if (tid < DM_)
            sm[OF_BI + tid] = bias[tid];
    }
    __syncthreads();

    // per-lane mask-init values for the 4 QK n-tiles (C cols 2tg, 2tg+1)
    float mo0[4], mo1[4];
#pragma unroll
    for (int nt = 0; nt < 4; nt++) {
        mo0[nt] = sm[OF_MO + nt * 8 + 2 * tg];
        mo1[nt] = sm[OF_MO + nt * 8 + 2 * tg + 1];
    }

    float* Psm = sm + OF_P + wid * 16 * PPAD;

#pragma unroll 1
    for (int t = 0; t < 2; t++) {
        const int rowbase = blockIdx.x * 128 + (wid * 2 + t) * 16;
        const float* Qb = Q + ((size_t)b * NQ_ + rowbase) * DM_;

        // ---- load Q A-fragments for all heads (batched for MLP) ----
        // q[h][ks*4+r]: r0=A[g][c], r1=A[g+8][c], r2=A[g][c+4], r3=A[g+8][c+4]
        float q[4][8];
#pragma unroll
        for (int h = 0; h < 4; h++) {
#pragma unroll
            for (int ks = 0; ks < 2; ks++) {
                int c = h * 16 + ks * 8 + tg;
                q[h][ks * 4 + 0] = Qb[(size_t)g * DM_ + c];
                q[h][ks * 4 + 1] = Qb[(size_t)(g + 8) * DM_ + c];
                q[h][ks * 4 + 2] = Qb[(size_t)g * DM_ + c + 4];
                q[h][ks * 4 + 3] = Qb[(size_t)(g + 8) * DM_ + c + 4];
            }
        }

        // output accumulators: 8 n-tiles x m16n8 C fragments
        float d[8][4];
#pragma unroll
        for (int nt = 0; nt < 8; nt++) {
            d[nt][0] = 0.f; d[nt][1] = 0.f; d[nt][2] = 0.f; d[nt][3] = 0.f;
        }

#pragma unroll
        for (int h = 0; h < 4; h++) {
            // ---- A (Q) hi/lo split for this head ----
            uint32_t ahi[8], alo[8];
#pragma unroll
            for (int i = 0; i < 8; i++) {
                ahi[i] = hi_of(q[h][i]);
                alo[i] = lo_of(q[h][i], ahi[i]);
            }

            // ---- QK: C seeded with mask offsets, 3-term tf32 ----
            float c[4][4];
#pragma unroll
            for (int nt = 0; nt < 4; nt++) {
                c[nt][0] = mo0[nt]; c[nt][1] = mo1[nt];
                c[nt][2] = mo0[nt]; c[nt][3] = mo1[nt];
            }
#pragma unroll
            for (int ks = 0; ks < 2; ks++) {
#pragma unroll
                for (int nt = 0; nt < 4; nt++) {
                    float kb0 = sm[OF_K + (h * 16 + ks * 8 + tg)     * KPAD + nt * 8 + g];
                    float kb1 = sm[OF_K + (h * 16 + ks * 8 + tg + 4) * KPAD + nt * 8 + g];
                    uint32_t bh0 = hi_of(kb0), bh1 = hi_of(kb1);
                    uint32_t bl0 = lo_of(kb0, bh0), bl1 = lo_of(kb1, bh1);
                    mma_tf32(c[nt], ahi[ks*4+0], ahi[ks*4+1], ahi[ks*4+2], ahi[ks*4+3], bh0, bh1);
                    mma_tf32(c[nt], ahi[ks*4+0], ahi[ks*4+1], ahi[ks*4+2], ahi[ks*4+3], bl0, bl1);
                    mma_tf32(c[nt], alo[ks*4+0], alo[ks*4+1], alo[ks*4+2], alo[ks*4+3], bh0, bh1);
                }
            }

            // ---- softmax on C fragments (rows g and g+8) ----
            float e[4][4];
            float sA = 0.f, sB = 0.f;
#pragma unroll
            for (int nt = 0; nt < 4; nt++) {
                e[nt][0] = ex2f(c[nt][0] * LOG2E_OVER_SCALE);
                e[nt][1] = ex2f(c[nt][1] * LOG2E_OVER_SCALE);
                e[nt][2] = ex2f(c[nt][2] * LOG2E_OVER_SCALE);
                e[nt][3] = ex2f(c[nt][3] * LOG2E_OVER_SCALE);
                sA += e[nt][0] + e[nt][1];
                sB += e[nt][2] + e[nt][3];
            }
            sA += __shfl_xor_sync(0xffffffffu, sA, 1);
            sA += __shfl_xor_sync(0xffffffffu, sA, 2);
            sB += __shfl_xor_sync(0xffffffffu, sB, 1);
            sB += __shfl_xor_sync(0xffffffffu, sB, 2);
            float rsA = (sA > 0.f) ? rcpf(sA) : 0.f;   // all-masked -> P = 0
            float rsB = (sB > 0.f) ? rcpf(sB) : 0.f;

            // ---- P (C layout) -> smem ----
#pragma unroll
            for (int nt = 0; nt < 4; nt++) {
                float2 p0 = make_float2(e[nt][0] * rsA, e[nt][1] * rsA);
                float2 p1 = make_float2(e[nt][2] * rsB, e[nt][3] * rsB);
                *(float2*)&Psm[g * PPAD + nt * 8 + 2 * tg]       = p0;
                *(float2*)&Psm[(g + 8) * PPAD + nt * 8 + 2 * tg] = p1;
            }
            __syncwarp();

            // ---- P A-fragments (hi/lo) for GEMM2 ----
            uint32_t phi[16], plo[16];
#pragma unroll
            for (int k2 = 0; k2 < 4; k2++) {
                float p0 = Psm[g * PPAD       + k2 * 8 + tg];
                float p1 = Psm[(g + 8) * PPAD + k2 * 8 + tg];
                float p2 = Psm[g * PPAD       + k2 * 8 + tg + 4];
                float p3 = Psm[(g + 8) * PPAD + k2 * 8 + tg + 4];
                phi[k2*4+0] = hi_of(p0);  plo[k2*4+0] = lo_of(p0, phi[k2*4+0]);
                phi[k2*4+1] = hi_of(p1);  plo[k2*4+1] = lo_of(p1, phi[k2*4+1]);
                phi[k2*4+2] = hi_of(p2);  plo[k2*4+2] = lo_of(p2, phi[k2*4+2]);
                phi[k2*4+3] = hi_of(p3);  plo[k2*4+3] = lo_of(p3, phi[k2*4+3]);
            }
            __syncwarp();   // reads done before next head's stores

            // ---- GEMM2: D += P_h @ VW_h (3-term tf32) ----
#pragma unroll
            for (int nt = 0; nt < 8; nt++) {
#pragma unroll
                for (int k2 = 0; k2 < 4; k2++) {
                    int krow = h * 32 + k2 * 8;
                    float w0 = sm[OF_VW + (krow + tg)     * VWPAD + nt * 8 + g];
                    float w1 = sm[OF_VW + (krow + tg + 4) * VWPAD + nt * 8 + g];
                    uint32_t bh0 = hi_of(w0), bh1 = hi_of(w1);
                    uint32_t bl0 = lo_of(w0, bh0), bl1 = lo_of(w1, bh1);
                    mma_tf32(d[nt], phi[k2*4+0], phi[k2*4+1], phi[k2*4+2], phi[k2*4+3], bh0, bh1);
                    mma_tf32(d[nt], phi[k2*4+0], phi[k2*4+1], phi[k2*4+2], phi[k2*4+3], bl0, bl1);
                    mma_tf32(d[nt], plo[k2*4+0], plo[k2*4+1], plo[k2*4+2], plo[k2*4+3], bh0, bh1);
                }
            }
        }

        // ---------------- epilogue: add bias, store ----------------
        float* ob = out + ((size_t)b * NQ_ + rowbase) * DM_;
#pragma unroll
        for (int nt = 0; nt < 8; nt++) {
            float2 bb = *(float2*)&sm[OF_BI + nt * 8 + 2 * tg];
            float2 o0 = make_float2(d[nt][0] + bb.x, d[nt][1] + bb.y);
            float2 o1 = make_float2(d[nt][2] + bb.x, d[nt][3] + bb.y);
            *(float2*)&ob[(size_t)g * DM_ + nt * 8 + 2 * tg]       = o0;
            *(float2*)&ob[(size_t)(g + 8) * DM_ + nt * 8 + 2 * tg] = o1;
        }
    }
}

// ---------------------------------------------------------------------------

extern "C" void kernel_launch(void* const* d_in, const int* in_sizes, int n_in,
                              void* d_out, int out_size)
{
    const float* Q    = (const float*)d_in[0];
    const float* K    = (const float*)d_in[1];
    const float* V    = (const float*)d_in[2];
    const int*   mask = (const int*)d_in[3];
    const float* W    = (const float*)d_in[4];
    const float* bias = (const float*)d_in[5];
    float*       out  = (float*)d_out;

    static bool attr_set = false;
    if (!attr_set) {
        cudaFuncSetAttribute(mha_tc_kernel,
                             cudaFuncAttributeMaxDynamicSharedMemorySize,
                             SMEM_FLOATS * 4);
        attr_set = true;
    }

    vw_prep<<<B_, NTHREADS>>>(V, W);

    dim3 grid(NQ_ / 128, B_);
    mha_tc_kernel<<<grid, NTHREADS, SMEM_FLOATS * 4>>>(Q, K, mask, bias, out);
}

// round 9
// speedup vs baseline: 1.3841x; 1.3841x over previous
#include <cuda_runtime.h>
#include <cstdint>

// Problem constants
#define B_   32
#define NQ_  16384
#define NK_  31
#define DM_  64
#define H_   4
#define DH_  16

#define NTHREADS 128

// log2(e) / sqrt(d_head)
#define LOG2E_OVER_SCALE 0.36067376022224085f

// Padded smem pitches (floats) chosen for conflict-free fragment LDS
#define KPAD  40     // Ksm[64 d][40]
#define VWPAD 72     // VWsm[128 k][72]
#define PPAD  40     // Psm per warp [16 rows][40]

// smem float offsets
#define OF_VW 0                         // 128*72   = 9216
#define OF_K  9216                      // 64*40    = 2560
#define OF_P  11776                     // 4*16*40  = 2560
#define OF_MO 14336                     // 32
#define OF_BI 14368                     // 64
#define SMEM_FLOATS 14432               // 57728 bytes

// Precomputed VW = per-head V_h @ W_h^T, concatenated along k: [b][128 k][72]
__device__ float g_vw[B_ * 128 * VWPAD];

// ---------------- helpers ----------------

__device__ __forceinline__ uint32_t hi_of(float v) {
    return __float_as_uint(v) & 0xFFFFE000u;            // tf32-exact high part
}
__device__ __forceinline__ uint32_t lo_of(float v, uint32_t h) {
    return __float_as_uint(v - __uint_as_float(h));     // exact residual
}
__device__ __forceinline__ float ex2f(float x) {
    float y;
    asm("ex2.approx.ftz.f32 %0, %1;" : "=f"(y) : "f"(x));
    return y;
}
__device__ __forceinline__ float rcpf(float x) {
    float y;
    asm("rcp.approx.ftz.f32 %0, %1;" : "=f"(y) : "f"(x));
    return y;
}

// D += A(tf32) * B(tf32), m16n8k8, A row-major, B col-major, fp32 accumulate
__device__ __forceinline__ void mma_tf32(float d[4],
                                         uint32_t a0, uint32_t a1,
                                         uint32_t a2, uint32_t a3,
                                         uint32_t b0, uint32_t b1) {
    asm volatile(
        "mma.sync.aligned.m16n8k8.row.col.f32.tf32.tf32.f32 "
        "{%0,%1,%2,%3}, {%4,%5,%6,%7}, {%8,%9}, {%0,%1,%2,%3};"
        : "+f"(d[0]), "+f"(d[1]), "+f"(d[2]), "+f"(d[3])
        : "r"(a0), "r"(a1), "r"(a2), "r"(a3), "r"(b0), "r"(b1));
}

// ===========================================================================
// Prep: VW[b][k = h*32+key][n] = sum_i V[b][key][h*16+i] * W[n][h*16+i]
// Parallelized: grid (B_, 8); each CTA computes 1024 of the 8192 elements.
// ===========================================================================

__global__ void __launch_bounds__(NTHREADS)
vw_prep(const float* __restrict__ V, const float* __restrict__ W)
{
    const int b    = blockIdx.x;
    const int base = blockIdx.y * 1024;
#pragma unroll
    for (int it = 0; it < 8; it++) {
        int idx = base + it * NTHREADS + threadIdx.x;
        int k = idx >> 6;          // 0..127
        int n = idx & 63;
        int h = k >> 5, key = k & 31;
        float acc = 0.f;
        if (key < NK_) {
            const float* vp = V + ((size_t)b * NK_ + key) * DM_ + h * DH_;
            const float* wp = W + n * DM_ + h * DH_;
#pragma unroll
            for (int i = 0; i < DH_; i++) acc += vp[i] * wp[i];
        }
        g_vw[(size_t)b * 128 * VWPAD + k * VWPAD + n] = acc;
    }
}

// ===========================================================================
// Main: QK (tensor, 3xTF32) -> softmax (C-frag regs) -> P@VW (tensor, 3xTF32)
// Block = 128 threads (4 warps); each warp processes BOTH of its m16 tiles in
// one pass so every K/VW fragment load is shared across the two tiles.
// ===========================================================================

__global__ void __launch_bounds__(NTHREADS, 3)
mha_tc_kernel(const float* __restrict__ Q,
              const float* __restrict__ K,
              const int* __restrict__ mask,
              const float* __restrict__ bias,
              float* __restrict__ out)
{
    extern __shared__ float sm[];
    const int tid  = threadIdx.x;
    const int wid  = tid >> 5;
    const int lane = tid & 31;
    const int g    = lane >> 2;      // groupID (row within half-tile)
    const int tg   = lane & 3;       // threadID in group
    const int b    = blockIdx.y;

    // ---------------- stage VW, K^T, mask offsets, bias ----------------
    {
        const float4* src = (const float4*)(g_vw + (size_t)b * 128 * VWPAD);
        float4* dst = (float4*)(sm + OF_VW);
        for (int i = tid; i < 128 * VWPAD / 4; i += NTHREADS) dst[i] = src[i];

        const float* Kb = K + (size_t)b * NK_ * DM_;
        for (int i = tid; i < DM_ * 32; i += NTHREADS) {
            int d = i >> 5, key = i & 31;
            sm[OF_K + d * KPAD + key] = (key < NK_) ? Kb[key * DM_ + d] : 0.f;
        }
        if (tid < 32)
            sm[OF_MO + tid] = (tid < NK_ && mask[b * NK_ + tid] != 0) ? 0.f : -1e30f;
        if (tid < DM_)
            sm[OF_BI + tid] = bias[tid];
    }
    __syncthreads();

    // per-lane mask-init values for the 4 QK n-tiles (C cols 2tg, 2tg+1)
    float mo0[4], mo1[4];
#pragma unroll
    for (int nt = 0; nt < 4; nt++) {
        mo0[nt] = sm[OF_MO + nt * 8 + 2 * tg];
        mo1[nt] = sm[OF_MO + nt * 8 + 2 * tg + 1];
    }

    float* Psm = sm + OF_P + wid * 16 * PPAD;

    const int rowbase = blockIdx.x * 128 + wid * 32;   // tile t covers +t*16
    const float* Qb = Q + ((size_t)b * NQ_ + rowbase) * DM_;

    // output accumulators: 2 tiles x 8 n-tiles x m16n8 C fragments
    float d[2][8][4];
#pragma unroll
    for (int t = 0; t < 2; t++)
#pragma unroll
        for (int nt = 0; nt < 8; nt++) {
            d[t][nt][0] = 0.f; d[t][nt][1] = 0.f;
            d[t][nt][2] = 0.f; d[t][nt][3] = 0.f;
        }

#pragma unroll
    for (int h = 0; h < 4; h++) {
        // ---- Q A-fragments (hi/lo) for this head, both tiles ----
        uint32_t ahi[2][8], alo[2][8];
#pragma unroll
        for (int t = 0; t < 2; t++) {
            const float* Qt = Qb + (size_t)t * 16 * DM_;
#pragma unroll
            for (int ks = 0; ks < 2; ks++) {
                int cc = h * 16 + ks * 8 + tg;
                float v0 = Qt[(size_t)g * DM_ + cc];
                float v1 = Qt[(size_t)(g + 8) * DM_ + cc];
                float v2 = Qt[(size_t)g * DM_ + cc + 4];
                float v3 = Qt[(size_t)(g + 8) * DM_ + cc + 4];
                ahi[t][ks*4+0] = hi_of(v0);  alo[t][ks*4+0] = lo_of(v0, ahi[t][ks*4+0]);
                ahi[t][ks*4+1] = hi_of(v1);  alo[t][ks*4+1] = lo_of(v1, ahi[t][ks*4+1]);
                ahi[t][ks*4+2] = hi_of(v2);  alo[t][ks*4+2] = lo_of(v2, ahi[t][ks*4+2]);
                ahi[t][ks*4+3] = hi_of(v3);  alo[t][ks*4+3] = lo_of(v3, ahi[t][ks*4+3]);
            }
        }

        // ---- QK: C seeded with mask offsets, 3-term tf32, K frags shared ----
        float c[2][4][4];
#pragma unroll
        for (int t = 0; t < 2; t++)
#pragma unroll
            for (int nt = 0; nt < 4; nt++) {
                c[t][nt][0] = mo0[nt]; c[t][nt][1] = mo1[nt];
                c[t][nt][2] = mo0[nt]; c[t][nt][3] = mo1[nt];
            }
#pragma unroll
        for (int ks = 0; ks < 2; ks++) {
#pragma unroll
            for (int nt = 0; nt < 4; nt++) {
                float kb0 = sm[OF_K + (h * 16 + ks * 8 + tg)     * KPAD + nt * 8 + g];
                float kb1 = sm[OF_K + (h * 16 + ks * 8 + tg + 4) * KPAD + nt * 8 + g];
                uint32_t bh0 = hi_of(kb0), bh1 = hi_of(kb1);
                uint32_t bl0 = lo_of(kb0, bh0), bl1 = lo_of(kb1, bh1);
#pragma unroll
                for (int t = 0; t < 2; t++) {
                    mma_tf32(c[t][nt], ahi[t][ks*4+0], ahi[t][ks*4+1],
                                       ahi[t][ks*4+2], ahi[t][ks*4+3], bh0, bh1);
                    mma_tf32(c[t][nt], ahi[t][ks*4+0], ahi[t][ks*4+1],
                                       ahi[t][ks*4+2], ahi[t][ks*4+3], bl0, bl1);
                    mma_tf32(c[t][nt], alo[t][ks*4+0], alo[t][ks*4+1],
                                       alo[t][ks*4+2], alo[t][ks*4+3], bh0, bh1);
                }
            }
        }

        // ---- softmax + C->A transpose per tile (shared Psm buffer) ----
        uint32_t phi[2][16], plo[2][16];
#pragma unroll
        for (int t = 0; t < 2; t++) {
            float e[4][4];
            float sA = 0.f, sB = 0.f;
#pragma unroll
            for (int nt = 0; nt < 4; nt++) {
                e[nt][0] = ex2f(c[t][nt][0] * LOG2E_OVER_SCALE);
                e[nt][1] = ex2f(c[t][nt][1] * LOG2E_OVER_SCALE);
                e[nt][2] = ex2f(c[t][nt][2] * LOG2E_OVER_SCALE);
                e[nt][3] = ex2f(c[t][nt][3] * LOG2E_OVER_SCALE);
                sA += e[nt][0] + e[nt][1];
                sB += e[nt][2] + e[nt][3];
            }
            sA += __shfl_xor_sync(0xffffffffu, sA, 1);
            sA += __shfl_xor_sync(0xffffffffu, sA, 2);
            sB += __shfl_xor_sync(0xffffffffu, sB, 1);
            sB += __shfl_xor_sync(0xffffffffu, sB, 2);
            float rsA = (sA > 0.f) ? rcpf(sA) : 0.f;   // all-masked -> P = 0
            float rsB = (sB > 0.f) ? rcpf(sB) : 0.f;

#pragma unroll
            for (int nt = 0; nt < 4; nt++) {
                float2 p0 = make_float2(e[nt][0] * rsA, e[nt][1] * rsA);
                float2 p1 = make_float2(e[nt][2] * rsB, e[nt][3] * rsB);
                *(float2*)&Psm[g * PPAD + nt * 8 + 2 * tg]       = p0;
                *(float2*)&Psm[(g + 8) * PPAD + nt * 8 + 2 * tg] = p1;
            }
            __syncwarp();

#pragma unroll
            for (int k2 = 0; k2 < 4; k2++) {
                float p0 = Psm[g * PPAD       + k2 * 8 + tg];
                float p1 = Psm[(g + 8) * PPAD + k2 * 8 + tg];
                float p2 = Psm[g * PPAD       + k2 * 8 + tg + 4];
                float p3 = Psm[(g + 8) * PPAD + k2 * 8 + tg + 4];
                phi[t][k2*4+0] = hi_of(p0);  plo[t][k2*4+0] = lo_of(p0, phi[t][k2*4+0]);
                phi[t][k2*4+1] = hi_of(p1);  plo[t][k2*4+1] = lo_of(p1, phi[t][k2*4+1]);
                phi[t][k2*4+2] = hi_of(p2);  plo[t][k2*4+2] = lo_of(p2, phi[t][k2*4+2]);
                phi[t][k2*4+3] = hi_of(p3);  plo[t][k2*4+3] = lo_of(p3, phi[t][k2*4+3]);
            }
            __syncwarp();   // reads done before this buffer is reused
        }

        // ---- GEMM2: D += P_h @ VW_h (3-term tf32), VW frags shared ----
#pragma unroll
        for (int nt = 0; nt < 8; nt++) {
#pragma unroll
            for (int k2 = 0; k2 < 4; k2++) {
                int krow = h * 32 + k2 * 8;
                float w0 = sm[OF_VW + (krow + tg)     * VWPAD + nt * 8 + g];
                float w1 = sm[OF_VW + (krow + tg + 4) * VWPAD + nt * 8 + g];
                uint32_t bh0 = hi_of(w0), bh1 = hi_of(w1);
                uint32_t bl0 = lo_of(w0, bh0), bl1 = lo_of(w1, bh1);
#pragma unroll
                for (int t = 0; t < 2; t++) {
                    mma_tf32(d[t][nt], phi[t][k2*4+0], phi[t][k2*4+1],
                                       phi[t][k2*4+2], phi[t][k2*4+3], bh0, bh1);
                    mma_tf32(d[t][nt], phi[t][k2*4+0], phi[t][k2*4+1],
                                       phi[t][k2*4+2], phi[t][k2*4+3], bl0, bl1);
                    mma_tf32(d[t][nt], plo[t][k2*4+0], plo[t][k2*4+1],
                                       plo[t][k2*4+2], plo[t][k2*4+3], bh0, bh1);
                }
            }
        }
    }

    // ---------------- epilogue: add bias, store both tiles ----------------
#pragma unroll
    for (int t = 0; t < 2; t++) {
        float* ob = out + ((size_t)b * NQ_ + rowbase + t * 16) * DM_;
#pragma unroll
        for (int nt = 0; nt < 8; nt++) {
            float2 bb = *(float2*)&sm[OF_BI + nt * 8 + 2 * tg];
            float2 o0 = make_float2(d[t][nt][0] + bb.x, d[t][nt][1] + bb.y);
            float2 o1 = make_float2(d[t][nt][2] + bb.x, d[t][nt][3] + bb.y);
            *(float2*)&ob[(size_t)g * DM_ + nt * 8 + 2 * tg]       = o0;
            *(float2*)&ob[(size_t)(g + 8) * DM_ + nt * 8 + 2 * tg] = o1;
        }
    }
}

// ---------------------------------------------------------------------------

extern "C" void kernel_launch(void* const* d_in, const int* in_sizes, int n_in,
                              void* d_out, int out_size)
{
    const float* Q    = (const float*)d_in[0];
    const float* K    = (const float*)d_in[1];
    const float* V    = (const float*)d_in[2];
    const int*   mask = (const int*)d_in[3];
    const float* W    = (const float*)d_in[4];
    const float* bias = (const float*)d_in[5];
    float*       out  = (float*)d_out;

    static bool attr_set = false;
    if (!attr_set) {
        cudaFuncSetAttribute(mha_tc_kernel,
                             cudaFuncAttributeMaxDynamicSharedMemorySize,
                             SMEM_FLOATS * 4);
        attr_set = true;
    }

    dim3 gridP(B_, 8);
    vw_prep<<<gridP, NTHREADS>>>(V, W);

    dim3 grid(NQ_ / 128, B_);
    mha_tc_kernel<<<grid, NTHREADS, SMEM_FLOATS * 4>>>(Q, K, mask, bias, out);
}

// round 10
// speedup vs baseline: 1.4299x; 1.0330x over previous
#include <cuda_runtime.h>
#include <cstdint>

// Problem constants
#define B_   32
#define NQ_  16384
#define NK_  31
#define DM_  64
#define H_   4
#define DH_  16

#define NTHREADS 128

// log2(e) / sqrt(d_head)
#define LOG2E_OVER_SCALE 0.36067376022224085f

// Padded smem pitches (floats)
#define KPAD  40     // Ksm[64 d][40]
#define VWPAD 72     // VWsm[128 k][72]
#define PPAD  40     // Psm per warp [16 rows][40]
#define QPAD  68     // Qbuf per warp [16 rows][68] (bank = 4g+tg, conflict-free)

// smem float offsets
#define OF_VW 0                         // 128*72   = 9216
#define OF_K  9216                      // 64*40    = 2560
#define OF_P  11776                     // 4*16*40  = 2560
#define OF_MO 14336                     // 32
#define OF_BI 14368                     // 64
#define OF_QB 14432                     // 4*16*68  = 4352
#define SMEM_FLOATS 18784               // 75136 bytes (3 CTAs/SM: 225 KB)

// Precomputed VW = per-head V_h @ W_h^T, concatenated along k: [b][128 k][72]
__device__ float g_vw[B_ * 128 * VWPAD];

// ---------------- helpers ----------------

__device__ __forceinline__ uint32_t hi_of(float v) {
    return __float_as_uint(v) & 0xFFFFE000u;            // tf32-exact high part
}
__device__ __forceinline__ uint32_t lo_of(float v, uint32_t h) {
    return __float_as_uint(v - __uint_as_float(h));     // exact residual
}
__device__ __forceinline__ float ex2f(float x) {
    float y;
    asm("ex2.approx.ftz.f32 %0, %1;" : "=f"(y) : "f"(x));
    return y;
}
__device__ __forceinline__ float rcpf(float x) {
    float y;
    asm("rcp.approx.ftz.f32 %0, %1;" : "=f"(y) : "f"(x));
    return y;
}

// D += A(tf32) * B(tf32), m16n8k8, A row-major, B col-major, fp32 accumulate
__device__ __forceinline__ void mma_tf32(float d[4],
                                         uint32_t a0, uint32_t a1,
                                         uint32_t a2, uint32_t a3,
                                         uint32_t b0, uint32_t b1) {
    asm volatile(
        "mma.sync.aligned.m16n8k8.row.col.f32.tf32.tf32.f32 "
        "{%0,%1,%2,%3}, {%4,%5,%6,%7}, {%8,%9}, {%0,%1,%2,%3};"
        : "+f"(d[0]), "+f"(d[1]), "+f"(d[2]), "+f"(d[3])
        : "r"(a0), "r"(a1), "r"(a2), "r"(a3), "r"(b0), "r"(b1));
}

// ===========================================================================
// Prep: VW[b][k = h*32+key][n] = sum_i V[b][key][h*16+i] * W[n][h*16+i]
// grid (B_, 8); each CTA computes 1024 of the 8192 elements.
// ===========================================================================

__global__ void __launch_bounds__(NTHREADS)
vw_prep(const float* __restrict__ V, const float* __restrict__ W)
{
    const int b    = blockIdx.x;
    const int base = blockIdx.y * 1024;
#pragma unroll
    for (int it = 0; it < 8; it++) {
        int idx = base + it * NTHREADS + threadIdx.x;
        int k = idx >> 6;          // 0..127
        int n = idx & 63;
        int h = k >> 5, key = k & 31;
        float acc = 0.f;
        if (key < NK_) {
            const float* vp = V + ((size_t)b * NK_ + key) * DM_ + h * DH_;
            const float* wp = W + n * DM_ + h * DH_;
#pragma unroll
            for (int i = 0; i < DH_; i++) acc += vp[i] * wp[i];
        }
        g_vw[(size_t)b * 128 * VWPAD + k * VWPAD + n] = acc;
    }
}

// ===========================================================================
// Main: QK (tensor, 3xTF32) -> softmax -> P@VW (tensor, 2-term: Phi only)
// Q and output staged through a per-warp smem buffer for coalesced gmem I/O.
// ===========================================================================

__global__ void __launch_bounds__(NTHREADS, 3)
mha_tc_kernel(const float* __restrict__ Q,
              const float* __restrict__ K,
              const int* __restrict__ mask,
              const float* __restrict__ bias,
              float* __restrict__ out)
{
    extern __shared__ float sm[];
    const int tid  = threadIdx.x;
    const int wid  = tid >> 5;
    const int lane = tid & 31;
    const int g    = lane >> 2;      // groupID (row within half-tile)
    const int tg   = lane & 3;       // threadID in group
    const int b    = blockIdx.y;

    // ---------------- stage VW, K^T, mask offsets, bias ----------------
    {
        const float4* src = (const float4*)(g_vw + (size_t)b * 128 * VWPAD);
        float4* dst = (float4*)(sm + OF_VW);
        for (int i = tid; i < 128 * VWPAD / 4; i += NTHREADS) dst[i] = src[i];

        const float* Kb = K + (size_t)b * NK_ * DM_;
        for (int i = tid; i < DM_ * 32; i += NTHREADS) {
            int d = i >> 5, key = i & 31;
            sm[OF_K + d * KPAD + key] = (key < NK_) ? Kb[key * DM_ + d] : 0.f;
        }
        if (tid < 32)
            sm[OF_MO + tid] = (tid < NK_ && mask[b * NK_ + tid] != 0) ? 0.f : -1e30f;
        if (tid < DM_)
            sm[OF_BI + tid] = bias[tid];
    }
    __syncthreads();

    // per-lane mask-init values for the 4 QK n-tiles (C cols 2tg, 2tg+1)
    float mo0[4], mo1[4];
#pragma unroll
    for (int nt = 0; nt < 4; nt++) {
        mo0[nt] = sm[OF_MO + nt * 8 + 2 * tg];
        mo1[nt] = sm[OF_MO + nt * 8 + 2 * tg + 1];
    }

    float* Psm  = sm + OF_P  + wid * 16 * PPAD;
    float* Qbuf = sm + OF_QB + wid * 16 * QPAD;

    const int rowbase = blockIdx.x * 128 + wid * 32;   // tile t covers +t*16
    const float* Qb = Q + ((size_t)b * NQ_ + rowbase) * DM_;

    // output accumulators: 2 tiles x 8 n-tiles x m16n8 C fragments
    float d[2][8][4];
#pragma unroll
    for (int t = 0; t < 2; t++)
#pragma unroll
        for (int nt = 0; nt < 8; nt++) {
            d[t][nt][0] = 0.f; d[t][nt][1] = 0.f;
            d[t][nt][2] = 0.f; d[t][nt][3] = 0.f;
        }

    // ---- stage Q for both tiles & keep per-head fragments in regs ----
    // (loaded per tile to bound the buffer at 16 rows)
    float qv[2][4][8];   // [tile][head][frag slot]
#pragma unroll
    for (int t = 0; t < 2; t++) {
        const float* Qt = Qb + (size_t)t * 16 * DM_;
        // coalesced: 2 rows per iteration, 8 iterations for 16 rows
#pragma unroll
        for (int i = 0; i < 8; i++) {
            int idx  = i * 32 + lane;
            int row  = idx >> 4;
            int col4 = idx & 15;
            float4 v = *(const float4*)(Qt + (size_t)row * DM_ + col4 * 4);
            *(float4*)(Qbuf + row * QPAD + col4 * 4) = v;
        }
        __syncwarp();
#pragma unroll
        for (int h = 0; h < 4; h++) {
#pragma unroll
            for (int ks = 0; ks < 2; ks++) {
                int cc = h * 16 + ks * 8 + tg;
                qv[t][h][ks*4+0] = Qbuf[g * QPAD + cc];
                qv[t][h][ks*4+1] = Qbuf[(g + 8) * QPAD + cc];
                qv[t][h][ks*4+2] = Qbuf[g * QPAD + cc + 4];
                qv[t][h][ks*4+3] = Qbuf[(g + 8) * QPAD + cc + 4];
            }
        }
        __syncwarp();
    }

#pragma unroll
    for (int h = 0; h < 4; h++) {
        // ---- Q A-fragments (hi/lo) for this head, both tiles ----
        uint32_t ahi[2][8], alo[2][8];
#pragma unroll
        for (int t = 0; t < 2; t++)
#pragma unroll
            for (int i = 0; i < 8; i++) {
                ahi[t][i] = hi_of(qv[t][h][i]);
                alo[t][i] = lo_of(qv[t][h][i], ahi[t][i]);
            }

        // ---- QK: C seeded with mask offsets, 3-term tf32, K frags shared ----
        float c[2][4][4];
#pragma unroll
        for (int t = 0; t < 2; t++)
#pragma unroll
            for (int nt = 0; nt < 4; nt++) {
                c[t][nt][0] = mo0[nt]; c[t][nt][1] = mo1[nt];
                c[t][nt][2] = mo0[nt]; c[t][nt][3] = mo1[nt];
            }
#pragma unroll
        for (int ks = 0; ks < 2; ks++) {
#pragma unroll
            for (int nt = 0; nt < 4; nt++) {
                float kb0 = sm[OF_K + (h * 16 + ks * 8 + tg)     * KPAD + nt * 8 + g];
                float kb1 = sm[OF_K + (h * 16 + ks * 8 + tg + 4) * KPAD + nt * 8 + g];
                uint32_t bh0 = hi_of(kb0), bh1 = hi_of(kb1);
                uint32_t bl0 = lo_of(kb0, bh0), bl1 = lo_of(kb1, bh1);
#pragma unroll
                for (int t = 0; t < 2; t++) {
                    mma_tf32(c[t][nt], ahi[t][ks*4+0], ahi[t][ks*4+1],
                                       ahi[t][ks*4+2], ahi[t][ks*4+3], bh0, bh1);
                    mma_tf32(c[t][nt], ahi[t][ks*4+0], ahi[t][ks*4+1],
                                       ahi[t][ks*4+2], ahi[t][ks*4+3], bl0, bl1);
                    mma_tf32(c[t][nt], alo[t][ks*4+0], alo[t][ks*4+1],
                                       alo[t][ks*4+2], alo[t][ks*4+3], bh0, bh1);
                }
            }
        }

        // ---- softmax + C->A transpose per tile (P as tf32-hi only) ----
        uint32_t phi[2][16];
#pragma unroll
        for (int t = 0; t < 2; t++) {
            float e[4][4];
            float sA = 0.f, sB = 0.f;
#pragma unroll
            for (int nt = 0; nt < 4; nt++) {
                e[nt][0] = ex2f(c[t][nt][0] * LOG2E_OVER_SCALE);
                e[nt][1] = ex2f(c[t][nt][1] * LOG2E_OVER_SCALE);
                e[nt][2] = ex2f(c[t][nt][2] * LOG2E_OVER_SCALE);
                e[nt][3] = ex2f(c[t][nt][3] * LOG2E_OVER_SCALE);
                sA += e[nt][0] + e[nt][1];
                sB += e[nt][2] + e[nt][3];
            }
            sA += __shfl_xor_sync(0xffffffffu, sA, 1);
            sA += __shfl_xor_sync(0xffffffffu, sA, 2);
            sB += __shfl_xor_sync(0xffffffffu, sB, 1);
            sB += __shfl_xor_sync(0xffffffffu, sB, 2);
            float rsA = (sA > 0.f) ? rcpf(sA) : 0.f;   // all-masked -> P = 0
            float rsB = (sB > 0.f) ? rcpf(sB) : 0.f;

#pragma unroll
            for (int nt = 0; nt < 4; nt++) {
                float2 p0 = make_float2(e[nt][0] * rsA, e[nt][1] * rsA);
                float2 p1 = make_float2(e[nt][2] * rsB, e[nt][3] * rsB);
                *(float2*)&Psm[g * PPAD + nt * 8 + 2 * tg]       = p0;
                *(float2*)&Psm[(g + 8) * PPAD + nt * 8 + 2 * tg] = p1;
            }
            __syncwarp();

#pragma unroll
            for (int k2 = 0; k2 < 4; k2++) {
                phi[t][k2*4+0] = hi_of(Psm[g * PPAD       + k2 * 8 + tg]);
                phi[t][k2*4+1] = hi_of(Psm[(g + 8) * PPAD + k2 * 8 + tg]);
                phi[t][k2*4+2] = hi_of(Psm[g * PPAD       + k2 * 8 + tg + 4]);
                phi[t][k2*4+3] = hi_of(Psm[(g + 8) * PPAD + k2 * 8 + tg + 4]);
            }
            __syncwarp();   // reads done before this buffer is reused
        }

        // ---- GEMM2: D += P_h @ VW_h (2-term: Phi x (VWhi + VWlo)) ----
#pragma unroll
        for (int nt = 0; nt < 8; nt++) {
#pragma unroll
            for (int k2 = 0; k2 < 4; k2++) {
                int krow = h * 32 + k2 * 8;
                float w0 = sm[OF_VW + (krow + tg)     * VWPAD + nt * 8 + g];
                float w1 = sm[OF_VW + (krow + tg + 4) * VWPAD + nt * 8 + g];
                uint32_t bh0 = hi_of(w0), bh1 = hi_of(w1);
                uint32_t bl0 = lo_of(w0, bh0), bl1 = lo_of(w1, bh1);
#pragma unroll
                for (int t = 0; t < 2; t++) {
                    mma_tf32(d[t][nt], phi[t][k2*4+0], phi[t][k2*4+1],
                                       phi[t][k2*4+2], phi[t][k2*4+3], bh0, bh1);
                    mma_tf32(d[t][nt], phi[t][k2*4+0], phi[t][k2*4+1],
                                       phi[t][k2*4+2], phi[t][k2*4+3], bl0, bl1);
                }
            }
        }
    }

    // ---------------- epilogue: stage through Qbuf, coalesced STG ----------
#pragma unroll
    for (int t = 0; t < 2; t++) {
#pragma unroll
        for (int nt = 0; nt < 8; nt++) {
            *(float2*)&Qbuf[g * QPAD + nt * 8 + 2 * tg] =
                make_float2(d[t][nt][0], d[t][nt][1]);
            *(float2*)&Qbuf[(g + 8) * QPAD + nt * 8 + 2 * tg] =
                make_float2(d[t][nt][2], d[t][nt][3]);
        }
        __syncwarp();

        float* ob = out + ((size_t)b * NQ_ + rowbase + t * 16) * DM_;
#pragma unroll
        for (int i = 0; i < 8; i++) {
            int idx  = i * 32 + lane;
            int row  = idx >> 4;
            int col4 = idx & 15;
            float4 v  = *(const float4*)(Qbuf + row * QPAD + col4 * 4);
            float4 bb = *(const float4*)(sm + OF_BI + col4 * 4);
            v.x += bb.x; v.y += bb.y; v.z += bb.z; v.w += bb.w;
            *(float4*)(ob + (size_t)row * DM_ + col4 * 4) = v;
        }
        __syncwarp();
    }
}

// ---------------------------------------------------------------------------

extern "C" void kernel_launch(void* const* d_in, const int* in_sizes, int n_in,
                              void* d_out, int out_size)
{
    const float* Q    = (const float*)d_in[0];
    const float* K    = (const float*)d_in[1];
    const float* V    = (const float*)d_in[2];
    const int*   mask = (const int*)d_in[3];
    const float* W    = (const float*)d_in[4];
    const float* bias = (const float*)d_in[5];
    float*       out  = (float*)d_out;

    static bool attr_set = false;
    if (!attr_set) {
        cudaFuncSetAttribute(mha_tc_kernel,
                             cudaFuncAttributeMaxDynamicSharedMemorySize,
                             SMEM_FLOATS * 4);
        attr_set = true;
    }

    dim3 gridP(B_, 8);
    vw_prep<<<gridP, NTHREADS>>>(V, W);

    dim3 grid(NQ_ / 128, B_);
    mha_tc_kernel<<<grid, NTHREADS, SMEM_FLOATS * 4>>>(Q, K, mask, bias, out);
}

// round 11
// speedup vs baseline: 1.9561x; 1.3680x over previous
#include <cuda_runtime.h>
#include <cuda_fp16.h>
#include <cstdint>

// Problem constants
#define B_   32
#define NQ_  16384
#define NK_  31
#define DM_  64
#define H_   4

#define NTHREADS 256                     // 8 warps; each warp: 32 rows (2 m16 tiles)

// log2(e) / sqrt(d_head)
#define LOG2E_OVER_SCALE 0.36067376022224085f

// ---- smem layout (uint32 units) ----
#define OF_VWH 0                         // [64 k2][72]  half2 hi of VW
#define OF_VWL 4608                      // [64 k2][72]  half2 lo
#define OF_KH  9216                      // [32 d2][40]  half2 hi of K^T
#define OF_KL  10496
#define OF_MO  11776                     // 32 floats (0 or -1e30)
#define OF_BI  11808                     // 64 floats
#define OF_WB  11872                     // 8 warps x 1792
#define SMEM_U32 (11872 + 8 * 1792)      // 26208 u32 = 104832 B (2 CTAs/SM)

// per-warp buffer (1792 u32): Q hi/lo half2 [16][36], P hi/lo half2 [16][20];
// after the mainloop the whole buffer is reused as float out-staging [16][68].
#define WB_QH 0
#define WB_QL 576
#define WB_PH 1152
#define WB_PL 1472
#define WB_SIZE 1792
#define QPITCH 36
#define PPITCH 20
#define OPITCH 68

// Precomputed VW = per-head V_h @ W_h^T as packed half2 hi/lo: [b][64 k2][72]
__device__ uint32_t g_vwh[B_ * 64 * 72];
__device__ uint32_t g_vwl[B_ * 64 * 72];

// ---------------- helpers ----------------

__device__ __forceinline__ uint32_t f2h2(float a, float b) {
    __half2 h = __floats2half2_rn(a, b);
    return *(uint32_t*)&h;
}

// split (a,b) into packed half2 hi and exact-residual half2 lo (low half = a)
__device__ __forceinline__ void split2(float a, float b, uint32_t& hi, uint32_t& lo) {
    __half ha = __float2half_rn(a), hb = __float2half_rn(b);
    float la = a - __half2float(ha);
    float lb = b - __half2float(hb);
    __half2 hh = __halves2half2(ha, hb);
    hi = *(uint32_t*)&hh;
    lo = f2h2(la, lb);
}

__device__ __forceinline__ float ex2f(float x) {
    float y;
    asm("ex2.approx.ftz.f32 %0, %1;" : "=f"(y) : "f"(x));
    return y;
}
__device__ __forceinline__ float rcpf(float x) {
    float y;
    asm("rcp.approx.ftz.f32 %0, %1;" : "=f"(y) : "f"(x));
    return y;
}

// D += A(f16) * B(f16), m16n8k16, A row-major, B col-major, fp32 accumulate
__device__ __forceinline__ void mma_f16(float d[4],
                                        uint32_t a0, uint32_t a1,
                                        uint32_t a2, uint32_t a3,
                                        uint32_t b0, uint32_t b1) {
    asm volatile(
        "mma.sync.aligned.m16n8k16.row.col.f32.f16.f16.f32 "
        "{%0,%1,%2,%3}, {%4,%5,%6,%7}, {%8,%9}, {%0,%1,%2,%3};"
        : "+f"(d[0]), "+f"(d[1]), "+f"(d[2]), "+f"(d[3])
        : "r"(a0), "r"(a1), "r"(a2), "r"(a3), "r"(b0), "r"(b1));
}

// ===========================================================================
// Prep: VW[b][k = h*32+key][n] = sum_i V[b][key][h*16+i] * W[n][h*16+i]
// stored as half2 hi/lo packed along k-pairs. grid (B_, 4) x 128 threads.
// ===========================================================================

__global__ void __launch_bounds__(128)
vw_prep(const float* __restrict__ V, const float* __restrict__ W)
{
    const int b    = blockIdx.x;
    const int base = blockIdx.y * 1024;
#pragma unroll
    for (int it = 0; it < 8; it++) {
        int idx = base + it * 128 + threadIdx.x;   // 0..4095
        int k2 = idx >> 6;                         // 0..63 (k pair index)
        int n  = idx & 63;
        int k  = 2 * k2;
        int h  = k >> 5;
        int key0 = k & 31;                         // even; key1 = key0+1 (same head)
        float v0 = 0.f, v1 = 0.f;
        const float* wp = W + n * DM_ + h * 16;
        if (key0 < NK_) {
            const float* vp = V + ((size_t)b * NK_ + key0) * DM_ + h * 16;
#pragma unroll
            for (int i = 0; i < 16; i++) v0 += vp[i] * wp[i];
        }
        if (key0 + 1 < NK_) {
            const float* vp = V + ((size_t)b * NK_ + key0 + 1) * DM_ + h * 16;
#pragma unroll
            for (int i = 0; i < 16; i++) v1 += vp[i] * wp[i];
        }
        uint32_t hi, lo;
        split2(v0, v1, hi, lo);
        g_vwh[(b * 64 + k2) * 72 + n] = hi;
        g_vwl[(b * 64 + k2) * 72 + n] = lo;
    }
}

// ===========================================================================
// Main: QK (fp16 3-term, k16) -> softmax -> P@VW (fp16 3-term, k16)
// 256 threads / 8 warps; warp = 32 rows as two sequential m16 tiles.
// ===========================================================================

__global__ void __launch_bounds__(NTHREADS, 2)
mha_tc_kernel(const float* __restrict__ Q,
              const float* __restrict__ K,
              const int* __restrict__ mask,
              const float* __restrict__ bias,
              float* __restrict__ out)
{
    extern __shared__ uint32_t smu[];
    float* sm = (float*)smu;
    const int tid  = threadIdx.x;
    const int wid  = tid >> 5;
    const int lane = tid & 31;
    const int g    = lane >> 2;      // groupID
    const int tg   = lane & 3;       // threadID in group
    const int b    = blockIdx.y;

    // ---------------- CTA staging: VW (pre-split), K^T (split), mask, bias ----
    {
        const uint4* s0 = (const uint4*)(g_vwh + (size_t)b * 4608);
        const uint4* s1 = (const uint4*)(g_vwl + (size_t)b * 4608);
        uint4* d0 = (uint4*)(smu + OF_VWH);
        uint4* d1 = (uint4*)(smu + OF_VWL);
        for (int i = tid; i < 1152; i += NTHREADS) { d0[i] = s0[i]; d1[i] = s1[i]; }

        const float* Kb = K + (size_t)b * NK_ * DM_;
        for (int i = tid; i < 1024; i += NTHREADS) {
            int d2 = i >> 5, key = i & 31;
            float a = 0.f, c = 0.f;
            if (key < NK_) {
                const float* kp = Kb + (size_t)key * DM_ + 2 * d2;
                a = kp[0]; c = kp[1];
            }
            uint32_t hi, lo;
            split2(a, c, hi, lo);
            smu[OF_KH + d2 * 40 + key] = hi;
            smu[OF_KL + d2 * 40 + key] = lo;
        }
        if (tid < 32)
            sm[OF_MO + tid] = (tid < NK_ && mask[b * NK_ + tid] != 0) ? 0.f : -1e30f;
        if (tid < DM_)
            sm[OF_BI + tid] = bias[tid];
    }
    __syncthreads();

    // per-lane mask-init values for the 4 QK n-tiles (C cols 2tg, 2tg+1)
    float mo0[4], mo1[4];
#pragma unroll
    for (int nt = 0; nt < 4; nt++) {
        mo0[nt] = sm[OF_MO + nt * 8 + 2 * tg];
        mo1[nt] = sm[OF_MO + nt * 8 + 2 * tg + 1];
    }

    uint32_t* wb = smu + OF_WB + wid * WB_SIZE;

    const int rowbase = blockIdx.x * 256 + wid * 32;   // tile t covers +t*16

#pragma unroll 1
    for (int t = 0; t < 2; t++) {
        const float* Qt = Q + ((size_t)b * NQ_ + rowbase + t * 16) * DM_;

        // ---- stage Q tile (16x64): coalesced LDG.128, split to half2 hi/lo ----
#pragma unroll
        for (int i = 0; i < 8; i++) {
            int idx = i * 32 + lane;
            int row = idx >> 4;
            int c4  = idx & 15;
            float4 v = *(const float4*)(Qt + (size_t)row * DM_ + c4 * 4);
            uint32_t h0, l0, h1, l1;
            split2(v.x, v.y, h0, l0);
            split2(v.z, v.w, h1, l1);
            *(uint2*)&wb[WB_QH + row * QPITCH + 2 * c4] = make_uint2(h0, h1);
            *(uint2*)&wb[WB_QL + row * QPITCH + 2 * c4] = make_uint2(l0, l1);
        }
        __syncwarp();

        // output accumulators: 8 n-tiles x m16n8 C fragments
        float d[8][4];
#pragma unroll
        for (int nt = 0; nt < 8; nt++) {
            d[nt][0] = 0.f; d[nt][1] = 0.f; d[nt][2] = 0.f; d[nt][3] = 0.f;
        }

#pragma unroll
        for (int h = 0; h < 4; h++) {
            // ---- Q A-fragments (packed half2 hi/lo) from warp buffer ----
            uint32_t ah[4], al[4];
            {
                int c2 = h * 8 + tg;
                ah[0] = wb[WB_QH + g * QPITCH + c2];
                ah[1] = wb[WB_QH + (g + 8) * QPITCH + c2];
                ah[2] = wb[WB_QH + g * QPITCH + c2 + 4];
                ah[3] = wb[WB_QH + (g + 8) * QPITCH + c2 + 4];
                al[0] = wb[WB_QL + g * QPITCH + c2];
                al[1] = wb[WB_QL + (g + 8) * QPITCH + c2];
                al[2] = wb[WB_QL + g * QPITCH + c2 + 4];
                al[3] = wb[WB_QL + (g + 8) * QPITCH + c2 + 4];
            }

            // ---- QK: one k16 per head, 3-term fp16, C seeded with mask ----
            float c[4][4];
#pragma unroll
            for (int nt = 0; nt < 4; nt++) {
                c[nt][0] = mo0[nt]; c[nt][1] = mo1[nt];
                c[nt][2] = mo0[nt]; c[nt][3] = mo1[nt];
            }
#pragma unroll
            for (int nt = 0; nt < 4; nt++) {
                int r0 = (8 * h + tg) * 40 + nt * 8 + g;        // d2 = 8h+tg
                int r1 = (8 * h + tg + 4) * 40 + nt * 8 + g;    // d2 = 8h+tg+4
                uint32_t bh0 = smu[OF_KH + r0], bh1 = smu[OF_KH + r1];
                uint32_t bl0 = smu[OF_KL + r0], bl1 = smu[OF_KL + r1];
                mma_f16(c[nt], ah[0], ah[1], ah[2], ah[3], bh0, bh1);
                mma_f16(c[nt], ah[0], ah[1], ah[2], ah[3], bl0, bl1);
                mma_f16(c[nt], al[0], al[1], al[2], al[3], bh0, bh1);
            }

            // ---- softmax on C fragments (rows g, g+8) ----
            float e[4][4];
            float sA = 0.f, sB = 0.f;
#pragma unroll
            for (int nt = 0; nt < 4; nt++) {
                e[nt][0] = ex2f(c[nt][0] * LOG2E_OVER_SCALE);
                e[nt][1] = ex2f(c[nt][1] * LOG2E_OVER_SCALE);
                e[nt][2] = ex2f(c[nt][2] * LOG2E_OVER_SCALE);
                e[nt][3] = ex2f(c[nt][3] * LOG2E_OVER_SCALE);
                sA += e[nt][0] + e[nt][1];
                sB += e[nt][2] + e[nt][3];
            }
            sA += __shfl_xor_sync(0xffffffffu, sA, 1);
            sA += __shfl_xor_sync(0xffffffffu, sA, 2);
            sB += __shfl_xor_sync(0xffffffffu, sB, 1);
            sB += __shfl_xor_sync(0xffffffffu, sB, 2);
            float rsA = (sA > 0.f) ? rcpf(sA) : 0.f;   // all-masked -> P = 0
            float rsB = (sB > 0.f) ? rcpf(sB) : 0.f;

            // ---- P -> warp buffer as half2 hi/lo (C pairs are half2-ready) ----
#pragma unroll
            for (int nt = 0; nt < 4; nt++) {
                float p0 = e[nt][0] * rsA, p1 = e[nt][1] * rsA;
                float p2 = e[nt][2] * rsB, p3 = e[nt][3] * rsB;
                uint32_t hiA, loA, hiB, loB;
                split2(p0, p1, hiA, loA);
                split2(p2, p3, hiB, loB);
                wb[WB_PH + g * PPITCH + nt * 4 + tg]       = hiA;
                wb[WB_PL + g * PPITCH + nt * 4 + tg]       = loA;
                wb[WB_PH + (g + 8) * PPITCH + nt * 4 + tg] = hiB;
                wb[WB_PL + (g + 8) * PPITCH + nt * 4 + tg] = loB;
            }
            __syncwarp();

            // ---- GEMM2: D += P_h @ VW_h, two k16 chunks, 3-term fp16 ----
#pragma unroll
            for (int ch = 0; ch < 2; ch++) {
                uint32_t ph[4], pl[4];
                int c2 = 8 * ch + tg;
                ph[0] = wb[WB_PH + g * PPITCH + c2];
                ph[1] = wb[WB_PH + (g + 8) * PPITCH + c2];
                ph[2] = wb[WB_PH + g * PPITCH + c2 + 4];
                ph[3] = wb[WB_PH + (g + 8) * PPITCH + c2 + 4];
                pl[0] = wb[WB_PL + g * PPITCH + c2];
                pl[1] = wb[WB_PL + (g + 8) * PPITCH + c2];
                pl[2] = wb[WB_PL + g * PPITCH + c2 + 4];
                pl[3] = wb[WB_PL + (g + 8) * PPITCH + c2 + 4];
#pragma unroll
                for (int nt = 0; nt < 8; nt++) {
                    int r0 = (16 * h + 8 * ch + tg) * 72 + nt * 8 + g;
                    int r1 = (16 * h + 8 * ch + tg + 4) * 72 + nt * 8 + g;
                    uint32_t bh0 = smu[OF_VWH + r0], bh1 = smu[OF_VWH + r1];
                    uint32_t bl0 = smu[OF_VWL + r0], bl1 = smu[OF_VWL + r1];
                    mma_f16(d[nt], ph[0], ph[1], ph[2], ph[3], bh0, bh1);
                    mma_f16(d[nt], ph[0], ph[1], ph[2], ph[3], bl0, bl1);
                    mma_f16(d[nt], pl[0], pl[1], pl[2], pl[3], bh0, bh1);
                }
            }
            __syncwarp();   // P buffer reads done before next head's stores
        }

        // ---- epilogue: stage fragments through warp buffer, coalesced STG ----
        float* ob = (float*)wb;           // reuse warp buffer as [16][68] floats
#pragma unroll
        for (int nt = 0; nt < 8; nt++) {
            *(float2*)&ob[g * OPITCH + nt * 8 + 2 * tg] =
                make_float2(d[nt][0], d[nt][1]);
            *(float2*)&ob[(g + 8) * OPITCH + nt * 8 + 2 * tg] =
                make_float2(d[nt][2], d[nt][3]);
        }
        __syncwarp();

        float* og = out + ((size_t)b * NQ_ + rowbase + t * 16) * DM_;
#pragma unroll
        for (int i = 0; i < 8; i++) {
            int idx = i * 32 + lane;
            int row = idx >> 4;
            int c4  = idx & 15;
            float4 v  = *(const float4*)&ob[row * OPITCH + c4 * 4];
            float4 bb = *(const float4*)&sm[OF_BI + c4 * 4];
            v.x += bb.x; v.y += bb.y; v.z += bb.z; v.w += bb.w;
            *(float4*)(og + (size_t)row * DM_ + c4 * 4) = v;
        }
        __syncwarp();      // buffer reused for next tile's Q staging
    }
}

// ---------------------------------------------------------------------------

extern "C" void kernel_launch(void* const* d_in, const int* in_sizes, int n_in,
                              void* d_out, int out_size)
{
    const float* Q    = (const float*)d_in[0];
    const float* K    = (const float*)d_in[1];
    const float* V    = (const float*)d_in[2];
    const int*   mask = (const int*)d_in[3];
    const float* W    = (const float*)d_in[4];
    const float* bias = (const float*)d_in[5];
    float*       out  = (float*)d_out;

    static bool attr_set = false;
    if (!attr_set) {
        cudaFuncSetAttribute(mha_tc_kernel,
                             cudaFuncAttributeMaxDynamicSharedMemorySize,
                             SMEM_U32 * 4);
        attr_set = true;
    }

    dim3 gridP(B_, 4);
    vw_prep<<<gridP, 128>>>(V, W);

    dim3 grid(NQ_ / 256, B_);
    mha_tc_kernel<<<grid, NTHREADS, SMEM_U32 * 4>>>(Q, K, mask, bias, out);
}

// round 12
// speedup vs baseline: 2.1070x; 1.0772x over previous
#include <cuda_runtime.h>
#include <cuda_fp16.h>
#include <cstdint>

// Problem constants
#define B_   32
#define NQ_  16384
#define NK_  31
#define DM_  64
#define H_   4

#define NTHREADS 256                     // 8 warps; each warp: 32 rows (2 m16 tiles)

// log2(e) / sqrt(d_head)
#define LOG2E_OVER_SCALE 0.36067376022224085f

// ---- smem layout ----
// VW4: [4h][2ch][4tg][66] uint4  (pitch 66 ≡ 2 mod 8 -> conflict-free LDS.128)
// K4 : [4h][4tg][34]     uint4  (pitch 34 ≡ 2 mod 8)
#define VW4_ENT 2112                     // (4*2*4)*66
#define K4_ENT  544                      // (4*4)*34
#define OF_VW4_U32 0                     // 8448 u32
#define OF_K4_U32  8448                  // 2176 u32
#define OF_MO      10624                 // 32 floats
#define OF_BI      10656                 // 64 floats
#define OF_WB      10720                 // 8 warps x 1152 u32
#define WB_SIZE    1152
#define SMEM_U32   (10720 + 8 * 1152)    // 19936 u32 = 79744 B (2 CTAs/SM)

// per-warp buffer: Q hi [16][36], Q lo [16][36]; reused as float out [16][68]
#define WB_QH 0
#define WB_QL 576
#define QPITCH 36
#define OPITCH 68

// Precomputed VW fragments: [b][2112] uint4 in the smem layout above
__device__ uint4 g_vw4[B_ * VW4_ENT];

// ---------------- helpers ----------------

__device__ __forceinline__ uint32_t f2h2(float a, float b) {
    __half2 h = __floats2half2_rn(a, b);
    return *(uint32_t*)&h;
}

// split (a,b) into packed half2 hi and exact-residual half2 lo (low half = a)
__device__ __forceinline__ void split2(float a, float b, uint32_t& hi, uint32_t& lo) {
    __half ha = __float2half_rn(a), hb = __float2half_rn(b);
    float la = a - __half2float(ha);
    float lb = b - __half2float(hb);
    __half2 hh = __halves2half2(ha, hb);
    hi = *(uint32_t*)&hh;
    lo = f2h2(la, lb);
}

__device__ __forceinline__ float ex2f(float x) {
    float y;
    asm("ex2.approx.ftz.f32 %0, %1;" : "=f"(y) : "f"(x));
    return y;
}
__device__ __forceinline__ float rcpf(float x) {
    float y;
    asm("rcp.approx.ftz.f32 %0, %1;" : "=f"(y) : "f"(x));
    return y;
}

// D += A(f16) * B(f16), m16n8k16, A row-major, B col-major, fp32 accumulate
__device__ __forceinline__ void mma_f16(float d[4],
                                        uint32_t a0, uint32_t a1,
                                        uint32_t a2, uint32_t a3,
                                        uint32_t b0, uint32_t b1) {
    asm volatile(
        "mma.sync.aligned.m16n8k16.row.col.f32.f16.f16.f32 "
        "{%0,%1,%2,%3}, {%4,%5,%6,%7}, {%8,%9}, {%0,%1,%2,%3};"
        : "+f"(d[0]), "+f"(d[1]), "+f"(d[2]), "+f"(d[3])
        : "r"(a0), "r"(a1), "r"(a2), "r"(a3), "r"(b0), "r"(b1));
}

// ===========================================================================
// Prep: build VW B-fragment uint4 table per batch.
// VW[k = 32h + key][n] = sum_i V[b][key][16h+i] * W[n][16h+i]
// entry (h,ch,tg,n) = (hi(k0,k0+1), hi(k0+8,k0+9), lo(..), lo(..)),
//   k0 = 16ch + 2tg (key index within head).
// grid (B_, 4) x 128 threads, 4 entries per thread.
// ===========================================================================

__global__ void __launch_bounds__(128)
vw_prep(const float* __restrict__ V, const float* __restrict__ W)
{
    const int b = blockIdx.x;
#pragma unroll
    for (int it = 0; it < 4; it++) {
        int r = blockIdx.y * 512 + it * 128 + threadIdx.x;   // 0..2047
        int n   = r & 63;
        int tgc = r >> 6;
        int tg  = tgc & 3;
        int ch  = (tgc >> 2) & 1;
        int h   = tgc >> 3;
        int k0  = 16 * ch + 2 * tg;

        const float* wp = W + n * DM_ + h * 16;
        float dd[4] = {0.f, 0.f, 0.f, 0.f};
        int keys[4] = {k0, k0 + 1, k0 + 8, k0 + 9};
#pragma unroll
        for (int j = 0; j < 4; j++) {
            if (keys[j] < NK_) {
                const float* vp = V + ((size_t)b * NK_ + keys[j]) * DM_ + h * 16;
                float acc = 0.f;
#pragma unroll
                for (int i = 0; i < 16; i++) acc += vp[i] * wp[i];
                dd[j] = acc;
            }
        }
        uint32_t h01, l01, h23, l23;
        split2(dd[0], dd[1], h01, l01);
        split2(dd[2], dd[3], h23, l23);
        g_vw4[b * VW4_ENT + ((h * 2 + ch) * 4 + tg) * 66 + n] =
            make_uint4(h01, h23, l01, l23);
    }
}

// ===========================================================================
// Main: QK (fp16 3-term) -> softmax -> direct C->A frag convert -> P@VW
// (fp16 3-term). All B-operands fetched as single LDS.128 uint4.
// ===========================================================================

__global__ void __launch_bounds__(NTHREADS, 2)
mha_tc_kernel(const float* __restrict__ Q,
              const float* __restrict__ K,
              const int* __restrict__ mask,
              const float* __restrict__ bias,
              float* __restrict__ out)
{
    extern __shared__ uint32_t smu[];
    float* sm = (float*)smu;
    uint4* sm4 = (uint4*)smu;
    const int tid  = threadIdx.x;
    const int wid  = tid >> 5;
    const int lane = tid & 31;
    const int g    = lane >> 2;      // groupID
    const int tg   = lane & 3;       // threadID in group
    const int b    = blockIdx.y;

    // ---------------- CTA staging ----------------
    {
        // VW fragment table (pre-built)
        const uint4* src = g_vw4 + (size_t)b * VW4_ENT;
        for (int i = tid; i < VW4_ENT; i += NTHREADS) sm4[i] = src[i];

        // K fragment table: entry (h,tg,key) =
        //   (hi(K[key][16h+2tg],+1), hi(K[key][16h+2tg+8],+9), lo.., lo..)
        const float* Kb = K + (size_t)b * NK_ * DM_;
        for (int i = tid; i < 512; i += NTHREADS) {
            int hh  = i >> 7;
            int rem = i & 127;
            int tt  = rem >> 5;
            int key = rem & 31;
            float f0 = 0.f, f1 = 0.f, f2 = 0.f, f3 = 0.f;
            if (key < NK_) {
                const float* kp = Kb + (size_t)key * DM_ + 16 * hh + 2 * tt;
                f0 = kp[0]; f1 = kp[1]; f2 = kp[8]; f3 = kp[9];
            }
            uint32_t h01, l01, h23, l23;
            split2(f0, f1, h01, l01);
            split2(f2, f3, h23, l23);
            sm4[2112 + (hh * 4 + tt) * 34 + key] = make_uint4(h01, h23, l01, l23);
        }
        if (tid < 32)
            sm[OF_MO + tid] = (tid < NK_ && mask[b * NK_ + tid] != 0) ? 0.f : -1e30f;
        if (tid < DM_)
            sm[OF_BI + tid] = bias[tid];
    }
    __syncthreads();

    // per-lane mask-init values for the 4 QK n-tiles (C cols 2tg, 2tg+1)
    float mo0[4], mo1[4];
#pragma unroll
    for (int nt = 0; nt < 4; nt++) {
        mo0[nt] = sm[OF_MO + nt * 8 + 2 * tg];
        mo1[nt] = sm[OF_MO + nt * 8 + 2 * tg + 1];
    }

    uint32_t* wb = smu + OF_WB + wid * WB_SIZE;
    const int rowbase = blockIdx.x * 256 + wid * 32;   // tile t covers +t*16

#pragma unroll 1
    for (int t = 0; t < 2; t++) {
        const float* Qt = Q + ((size_t)b * NQ_ + rowbase + t * 16) * DM_;

        // ---- stage Q tile (16x64): coalesced LDG.128, split to half2 hi/lo ----
#pragma unroll
        for (int i = 0; i < 8; i++) {
            int idx = i * 32 + lane;
            int row = idx >> 4;
            int c4  = idx & 15;
            float4 v = *(const float4*)(Qt + (size_t)row * DM_ + c4 * 4);
            uint32_t h0, l0, h1, l1;
            split2(v.x, v.y, h0, l0);
            split2(v.z, v.w, h1, l1);
            *(uint2*)&wb[WB_QH + row * QPITCH + 2 * c4] = make_uint2(h0, h1);
            *(uint2*)&wb[WB_QL + row * QPITCH + 2 * c4] = make_uint2(l0, l1);
        }
        __syncwarp();

        // output accumulators: 8 n-tiles x m16n8 C fragments
        float d[8][4];
#pragma unroll
        for (int nt = 0; nt < 8; nt++) {
            d[nt][0] = 0.f; d[nt][1] = 0.f; d[nt][2] = 0.f; d[nt][3] = 0.f;
        }

#pragma unroll
        for (int h = 0; h < 4; h++) {
            // ---- Q A-fragments (packed half2 hi/lo) from warp buffer ----
            uint32_t ah[4], al[4];
            {
                int c2 = h * 8 + tg;
                ah[0] = wb[WB_QH + g * QPITCH + c2];
                ah[1] = wb[WB_QH + (g + 8) * QPITCH + c2];
                ah[2] = wb[WB_QH + g * QPITCH + c2 + 4];
                ah[3] = wb[WB_QH + (g + 8) * QPITCH + c2 + 4];
                al[0] = wb[WB_QL + g * QPITCH + c2];
                al[1] = wb[WB_QL + (g + 8) * QPITCH + c2];
                al[2] = wb[WB_QL + g * QPITCH + c2 + 4];
                al[3] = wb[WB_QL + (g + 8) * QPITCH + c2 + 4];
            }

            // ---- QK: one k16 per head, 3-term fp16, C seeded with mask ----
            float c[4][4];
#pragma unroll
            for (int nt = 0; nt < 4; nt++) {
                c[nt][0] = mo0[nt]; c[nt][1] = mo1[nt];
                c[nt][2] = mo0[nt]; c[nt][3] = mo1[nt];
            }
#pragma unroll
            for (int nt = 0; nt < 4; nt++) {
                uint4 kv = sm4[2112 + (h * 4 + tg) * 34 + nt * 8 + g];
                mma_f16(c[nt], ah[0], ah[1], ah[2], ah[3], kv.x, kv.y);
                mma_f16(c[nt], ah[0], ah[1], ah[2], ah[3], kv.z, kv.w);
                mma_f16(c[nt], al[0], al[1], al[2], al[3], kv.x, kv.y);
            }

            // ---- softmax on C fragments (rows g, g+8) ----
            float e[4][4];
            float sA = 0.f, sB = 0.f;
#pragma unroll
            for (int nt = 0; nt < 4; nt++) {
                e[nt][0] = ex2f(c[nt][0] * LOG2E_OVER_SCALE);
                e[nt][1] = ex2f(c[nt][1] * LOG2E_OVER_SCALE);
                e[nt][2] = ex2f(c[nt][2] * LOG2E_OVER_SCALE);
                e[nt][3] = ex2f(c[nt][3] * LOG2E_OVER_SCALE);
                sA += e[nt][0] + e[nt][1];
                sB += e[nt][2] + e[nt][3];
            }
            sA += __shfl_xor_sync(0xffffffffu, sA, 1);
            sA += __shfl_xor_sync(0xffffffffu, sA, 2);
            sB += __shfl_xor_sync(0xffffffffu, sB, 1);
            sB += __shfl_xor_sync(0xffffffffu, sB, 2);
            float rsA = (sA > 0.f) ? rcpf(sA) : 0.f;   // all-masked -> P = 0
            float rsB = (sB > 0.f) ? rcpf(sB) : 0.f;

            // ---- P: direct C->A fragment conversion (no smem round trip) ----
            // chunk ch A-frags come from n-tiles 2ch (a0,a1) and 2ch+1 (a2,a3)
            uint32_t ph[2][4], pl[2][4];
#pragma unroll
            for (int ch = 0; ch < 2; ch++) {
                split2(e[2*ch][0]   * rsA, e[2*ch][1]   * rsA, ph[ch][0], pl[ch][0]);
                split2(e[2*ch][2]   * rsB, e[2*ch][3]   * rsB, ph[ch][1], pl[ch][1]);
                split2(e[2*ch+1][0] * rsA, e[2*ch+1][1] * rsA, ph[ch][2], pl[ch][2]);
                split2(e[2*ch+1][2] * rsB, e[2*ch+1][3] * rsB, ph[ch][3], pl[ch][3]);
            }

            // ---- GEMM2: D += P_h @ VW_h, two k16 chunks, 3-term fp16 ----
#pragma unroll
            for (int ch = 0; ch < 2; ch++) {
#pragma unroll
                for (int nt = 0; nt < 8; nt++) {
                    uint4 wv = sm4[((h * 2 + ch) * 4 + tg) * 66 + nt * 8 + g];
                    mma_f16(d[nt], ph[ch][0], ph[ch][1], ph[ch][2], ph[ch][3],
                            wv.x, wv.y);
                    mma_f16(d[nt], ph[ch][0], ph[ch][1], ph[ch][2], ph[ch][3],
                            wv.z, wv.w);
                    mma_f16(d[nt], pl[ch][0], pl[ch][1], pl[ch][2], pl[ch][3],
                            wv.x, wv.y);
                }
            }
        }

        // ---- epilogue: stage fragments through warp buffer, coalesced STG ----
        __syncwarp();                     // Q frag reads done before reuse
        float* ob = (float*)wb;           // reuse warp buffer as [16][68] floats
#pragma unroll
        for (int nt = 0; nt < 8; nt++) {
            *(float2*)&ob[g * OPITCH + nt * 8 + 2 * tg] =
                make_float2(d[nt][0], d[nt][1]);
            *(float2*)&ob[(g + 8) * OPITCH + nt * 8 + 2 * tg] =
                make_float2(d[nt][2], d[nt][3]);
        }
        __syncwarp();

        float* og = out + ((size_t)b * NQ_ + rowbase + t * 16) * DM_;
#pragma unroll
        for (int i = 0; i < 8; i++) {
            int idx = i * 32 + lane;
            int row = idx >> 4;
            int c4  = idx & 15;
            float4 v  = *(const float4*)&ob[row * OPITCH + c4 * 4];
            float4 bb = *(const float4*)&sm[OF_BI + c4 * 4];
            v.x += bb.x; v.y += bb.y; v.z += bb.z; v.w += bb.w;
            *(float4*)(og + (size_t)row * DM_ + c4 * 4) = v;
        }
        __syncwarp();      // buffer reused for next tile's Q staging
    }
}

// ---------------------------------------------------------------------------

extern "C" void kernel_launch(void* const* d_in, const int* in_sizes, int n_in,
                              void* d_out, int out_size)
{
    const float* Q    = (const float*)d_in[0];
    const float* K    = (const float*)d_in[1];
    const float* V    = (const float*)d_in[2];
    const int*   mask = (const int*)d_in[3];
    const float* W    = (const float*)d_in[4];
    const float* bias = (const float*)d_in[5];
    float*       out  = (float*)d_out;

    static bool attr_set = false;
    if (!attr_set) {
        cudaFuncSetAttribute(mha_tc_kernel,
                             cudaFuncAttributeMaxDynamicSharedMemorySize,
                             SMEM_U32 * 4);
        attr_set = true;
    }

    dim3 gridP(B_, 4);
    vw_prep<<<gridP, 128>>>(V, W);

    dim3 grid(NQ_ / 256, B_);
    mha_tc_kernel<<<grid, NTHREADS, SMEM_U32 * 4>>>(Q, K, mask, bias, out);
}